// round 14
// baseline (speedup 1.0000x reference)
#include <cuda_runtime.h>
#include <cuda_bf16.h>
#include <mma.h>
#include <math.h>
#include <stdint.h>

using namespace nvcuda;

#define NB   4
#define DIMD 1024
#define PQ   512
#define NH   16
#define PD   64

// ---- static device scratch ----
static __device__ float g_xds  [NB * PQ * DIMD];
static __device__ float g_pA   [DIMD];
static __device__ float g_pB   [DIMD];
static __device__ float g_ypart[16 * 2048 * 128];
static __device__ float g_RqA  [NB * PQ * PD];
static __device__ float g_RqB  [NB * PQ * PD];
static __device__ float g_CkA  [NB * PQ * PD];
static __device__ float g_CkB  [NB * PQ * PD];
static __device__ float g_dot  [(size_t)NB * NH * PQ * PQ];   // 64 MB
// bf16 hi/lo splits
static __device__ __nv_bfloat16 g_xhi [2048 * 1024];
static __device__ __nv_bfloat16 g_xlo [2048 * 1024];
static __device__ __nv_bfloat16 g_wqhi[1024 * 1024];
static __device__ __nv_bfloat16 g_wqlo[1024 * 1024];
static __device__ __nv_bfloat16 g_wkhi[1024 * 1024];
static __device__ __nv_bfloat16 g_wklo[1024 * 1024];
static __device__ __nv_bfloat16 g_qhi [2048 * 1024];
static __device__ __nv_bfloat16 g_qlo [2048 * 1024];
static __device__ __nv_bfloat16 g_khi [2048 * 1024];
static __device__ __nv_bfloat16 g_klo [2048 * 1024];

// ---- cp.async helpers ----
#define CP_ASYNC16(dst, src) \
    asm volatile("cp.async.cg.shared.global [%0], [%1], 16;" :: "r"(dst), "l"(src))
#define CP_COMMIT() asm volatile("cp.async.commit_group;")
#define CP_WAIT(n)  asm volatile("cp.async.wait_group %0;" :: "n"(n))

// ---- packed f32x2 FMA ----
#define FMA2(d, a, b, c) \
    asm("fma.rn.f32x2 %0, %1, %2, %3;" : "=l"(d) : "l"(a), "l"(b), "l"(c))
__device__ __forceinline__ unsigned long long pk2(float x, float y) {
    unsigned long long r;
    asm("mov.b64 %0, {%1, %2};" : "=l"(r) : "f"(x), "f"(y));
    return r;
}
__device__ __forceinline__ void upk2(float& x, float& y, unsigned long long r) {
    asm("mov.b64 {%0, %1}, %2;" : "=f"(x), "=f"(y) : "l"(r));
}

// ---- bf16 hi/lo split ----
__device__ __forceinline__ void split_store(const float4& v, __nv_bfloat16* hi,
                                            __nv_bfloat16* lo, size_t idx4) {
    float a[4] = {v.x, v.y, v.z, v.w};
    __nv_bfloat16 h[4], l[4];
#pragma unroll
    for (int e = 0; e < 4; e++) {
        h[e] = __float2bfloat16(a[e]);
        l[e] = __float2bfloat16(a[e] - __bfloat162float(h[e]));
    }
    *(uint2*)(hi + idx4 * 4) = *(uint2*)h;
    *(uint2*)(lo + idx4 * 4) = *(uint2*)l;
}

// ---------------- 1) front kernel: pool+split(x) | posenc | split(W) ----------------
__global__ void k_front(const float* __restrict__ x,
                        const float* __restrict__ Wpos, const float* __restrict__ bpos,
                        const float* __restrict__ Wq, const float* __restrict__ Wk) {
    int bx = blockIdx.x;
    int tid = threadIdx.x;
    if (bx < 2048) {
        int gid = bx * 256 + tid;
        int d4 = gid & 255;
        int bp = gid >> 8;
        const float4* xin = reinterpret_cast<const float4*>(x);
        size_t base = (size_t)bp * 4 * 256 + d4;
        float4 r0 = xin[base], r1 = xin[base + 256], r2 = xin[base + 512], r3 = xin[base + 768];
        float4 o;
        o.x = (r0.x + r1.x + r2.x + r3.x) * 0.25f;
        o.y = (r0.y + r1.y + r2.y + r3.y) * 0.25f;
        o.z = (r0.z + r1.z + r2.z + r3.z) * 0.25f;
        o.w = (r0.w + r1.w + r2.w + r3.w) * 0.25f;
        size_t idx4 = (size_t)bp * 256 + d4;
        reinterpret_cast<float4*>(g_xds)[idx4] = o;
        split_store(o, g_xhi, g_xlo, idx4);
    } else if (bx < 2052) {
        int hc = (bx - 2048) * 256 + tid;
        if (hc >= DIMD) return;
        float s1 = 0.f, s2 = 0.f;
#pragma unroll
        for (int j = 0; j < 32; j++) s1 += Wpos[hc * 64 + j];
#pragma unroll
        for (int j = 32; j < 64; j++) s2 += Wpos[hc * 64 + j];
        g_pA[hc] = s1 - s2 + bpos[hc];
        g_pB[hc] = s1 + bpos[hc];
    } else {
        int z = (bx - 2052) >> 10;
        int gid = ((bx - 2052) & 1023) * 256 + tid;
        const float4* src = reinterpret_cast<const float4*>(z ? Wk : Wq);
        __nv_bfloat16* hi = z ? g_wkhi : g_wqhi;
        __nv_bfloat16* lo = z ? g_wklo : g_wqlo;
        split_store(src[gid], hi, lo, gid);
    }
}

// ---------------- 3) projection GEMM: single-sync pipelined mainloop ----------------
#define PRS 80
#define PLD 40
#define PTILE (128 * PRS)
#define PSTG (4 * PTILE)
#define PRJ_SMEM (2 * PSTG)

__global__ __launch_bounds__(256, 2) void k_projmma() {
    extern __shared__ char smem[];
    int tid = threadIdx.x;
    int wid = tid >> 5;
    int m0 = blockIdx.y * 128;
    int n0 = blockIdx.x * 128;
    const __nv_bfloat16* Bhi = blockIdx.z ? g_wkhi : g_wqhi;
    const __nv_bfloat16* Blo = blockIdx.z ? g_wklo : g_wqlo;
    __nv_bfloat16* Chi = blockIdx.z ? g_khi : g_qhi;
    __nv_bfloat16* Clo = blockIdx.z ? g_klo : g_qlo;

    int wm = wid & 3;
    int wn = wid >> 2;
    uint32_t sbase = (uint32_t)__cvta_generic_to_shared(smem);
    int lr = tid >> 1;
    int lh = (tid & 1) * 2;

    wmma::fragment<wmma::accumulator, 16, 16, 16, float> acc[2][4];
#pragma unroll
    for (int i = 0; i < 2; i++)
#pragma unroll
        for (int j = 0; j < 4; j++) wmma::fill_fragment(acc[i][j], 0.f);

    auto loadchunk = [&](int c, int s) {
        size_t ga = (size_t)(m0 + lr) * 1024 + c * 32;
        size_t gb = (size_t)(n0 + lr) * 1024 + c * 32;
        uint32_t rowoff = s * PSTG + lr * PRS;
#pragma unroll
        for (int f = 0; f < 2; f++) {
            int fo = lh + f;
            CP_ASYNC16(sbase + rowoff + 0 * PTILE + fo * 16, (const char*)(g_xhi + ga) + fo * 16);
            CP_ASYNC16(sbase + rowoff + 1 * PTILE + fo * 16, (const char*)(g_xlo + ga) + fo * 16);
            CP_ASYNC16(sbase + rowoff + 2 * PTILE + fo * 16, (const char*)(Bhi + gb) + fo * 16);
            CP_ASYNC16(sbase + rowoff + 3 * PTILE + fo * 16, (const char*)(Blo + gb) + fo * 16);
        }
    };

    loadchunk(0, 0);
    CP_COMMIT();

    for (int c = 0; c < 32; c++) {
        CP_WAIT(0);
        __syncthreads();
        if (c < 31) {
            loadchunk(c + 1, (c + 1) & 1);
            CP_COMMIT();
        }
        int s = c & 1;
        const __nv_bfloat16* pAh = (const __nv_bfloat16*)(smem + s * PSTG + 0 * PTILE);
        const __nv_bfloat16* pAl = (const __nv_bfloat16*)(smem + s * PSTG + 1 * PTILE);
        const __nv_bfloat16* pBh = (const __nv_bfloat16*)(smem + s * PSTG + 2 * PTILE);
        const __nv_bfloat16* pBl = (const __nv_bfloat16*)(smem + s * PSTG + 3 * PTILE);
#pragma unroll
        for (int ks = 0; ks < 2; ks++) {
            wmma::fragment<wmma::matrix_a, 16, 16, 16, __nv_bfloat16, wmma::row_major> ah[2], al[2];
            wmma::fragment<wmma::matrix_b, 16, 16, 16, __nv_bfloat16, wmma::col_major> bh[4], bl[4];
#pragma unroll
            for (int i = 0; i < 2; i++) {
                int mrow = wm * 32 + i * 16;
                wmma::load_matrix_sync(ah[i], pAh + mrow * PLD + ks * 16, PLD);
                wmma::load_matrix_sync(al[i], pAl + mrow * PLD + ks * 16, PLD);
            }
#pragma unroll
            for (int j = 0; j < 4; j++) {
                int nrow = wn * 64 + j * 16;
                wmma::load_matrix_sync(bh[j], pBh + nrow * PLD + ks * 16, PLD);
                wmma::load_matrix_sync(bl[j], pBl + nrow * PLD + ks * 16, PLD);
            }
#pragma unroll
            for (int i = 0; i < 2; i++)
#pragma unroll
                for (int j = 0; j < 4; j++) {
                    wmma::mma_sync(acc[i][j], ah[i], bh[j], acc[i][j]);
                    wmma::mma_sync(acc[i][j], ah[i], bl[j], acc[i][j]);
                    wmma::mma_sync(acc[i][j], al[i], bh[j], acc[i][j]);
                }
        }
    }
    __syncthreads();

    float* Cs = (float*)smem;
#pragma unroll
    for (int i = 0; i < 2; i++)
#pragma unroll
        for (int j = 0; j < 4; j++)
            wmma::store_matrix_sync(Cs + (wm * 32 + i * 16) * 128 + wn * 64 + j * 16,
                                    acc[i][j], 128, wmma::mem_row_major);
    __syncthreads();
#pragma unroll
    for (int it = 0; it < 16; it++) {
        int idx = it * 256 + tid;
        int r = idx >> 5, c4 = idx & 31;
        float4 v = reinterpret_cast<const float4*>(Cs)[idx];
        size_t off4 = ((size_t)(m0 + r) * 1024 + n0) / 4 + c4;
        split_store(v, Chi, Clo, off4);
    }
}

// ---------------- 4) y partials: K split 16 ways ----------------
__global__ __launch_bounds__(256) void k_y(const float* __restrict__ Wyq,
                                           const float* __restrict__ Wyk) {
    __shared__ float As[16][132];
    __shared__ float Bs[16][132];
    int ks = blockIdx.x;
    int bm = blockIdx.y * 128;
    int tid = threadIdx.x;
    int lr = tid >> 1;
    int lc = (tid & 1) * 8;
    int tx = tid & 15;
    int ty = tid >> 4;
    float acc[8][8];
#pragma unroll
    for (int i = 0; i < 8; i++)
#pragma unroll
        for (int j = 0; j < 8; j++) acc[i][j] = 0.f;

    const float* aptr = g_xds + (size_t)(bm + lr) * DIMD + ks * 64 + lc;
    const float* brow = (lr < 64) ? (Wyq + (size_t)lr * DIMD) : (Wyk + (size_t)(lr - 64) * DIMD);
    const float* bptr = brow + ks * 64 + lc;

    for (int k0 = 0; k0 < 64; k0 += 16) {
        float4 a0 = *(const float4*)(aptr + k0);
        float4 a1 = *(const float4*)(aptr + k0 + 4);
        float4 b0 = *(const float4*)(bptr + k0);
        float4 b1 = *(const float4*)(bptr + k0 + 4);
        float av8[8] = {a0.x, a0.y, a0.z, a0.w, a1.x, a1.y, a1.z, a1.w};
#pragma unroll
        for (int e = 0; e < 8; e++)
            av8[e] = 0.5f * av8[e] * (1.f + erff(av8[e] * 0.70710678118654752f));
        __syncthreads();
#pragma unroll
        for (int e = 0; e < 8; e++) As[lc + e][lr] = av8[e];
        Bs[lc + 0][lr] = b0.x; Bs[lc + 1][lr] = b0.y;
        Bs[lc + 2][lr] = b0.z; Bs[lc + 3][lr] = b0.w;
        Bs[lc + 4][lr] = b1.x; Bs[lc + 5][lr] = b1.y;
        Bs[lc + 6][lr] = b1.z; Bs[lc + 7][lr] = b1.w;
        __syncthreads();
#pragma unroll
        for (int kk = 0; kk < 16; kk++) {
            float4 af0 = *(const float4*)&As[kk][ty * 4];
            float4 af1 = *(const float4*)&As[kk][64 + ty * 4];
            float4 bf0 = *(const float4*)&Bs[kk][tx * 4];
            float4 bf1 = *(const float4*)&Bs[kk][64 + tx * 4];
            float av[8] = {af0.x, af0.y, af0.z, af0.w, af1.x, af1.y, af1.z, af1.w};
            float bv[8] = {bf0.x, bf0.y, bf0.z, bf0.w, bf1.x, bf1.y, bf1.z, bf1.w};
#pragma unroll
            for (int i = 0; i < 8; i++)
#pragma unroll
                for (int j = 0; j < 8; j++) acc[i][j] += av[i] * bv[j];
        }
    }
#pragma unroll
    for (int i = 0; i < 8; i++) {
        int r = bm + (i < 4 ? ty * 4 + i : 64 + ty * 4 + (i - 4));
        float4 v0 = make_float4(acc[i][0], acc[i][1], acc[i][2], acc[i][3]);
        float4 v1 = make_float4(acc[i][4], acc[i][5], acc[i][6], acc[i][7]);
        *(float4*)&g_ypart[((size_t)ks * 2048 + r) * 128 + tx * 4]      = v0;
        *(float4*)&g_ypart[((size_t)ks * 2048 + r) * 128 + 64 + tx * 4] = v1;
    }
}

// ---------------- 5) row/col corrections ----------------
__global__ __launch_bounds__(128) void k_scalars(const float* __restrict__ qbias,
                                                 const float* __restrict__ kbias,
                                                 const float* __restrict__ Wout,
                                                 const float* __restrict__ bout) {
    __shared__ float sA[16], sB[16];
    int row = blockIdx.x;
    int z = blockIdx.y;
    const __nv_bfloat16* shi = z ? g_khi : g_qhi;
    const __nv_bfloat16* slo = z ? g_klo : g_qlo;
    const float* bias = z ? kbias : qbias;
    int t = threadIdx.x;

    uint4 hraw = *(const uint4*)(shi + (size_t)row * DIMD + t * 8);
    uint4 lraw = *(const uint4*)(slo + (size_t)row * DIMD + t * 8);
    const __nv_bfloat16* h8 = (const __nv_bfloat16*)&hraw;
    const __nv_bfloat16* l8 = (const __nv_bfloat16*)&lraw;
    float4 b0 = *(const float4*)(bias + t * 8);
    float4 b1 = *(const float4*)(bias + t * 8 + 4);
    float4 pa0 = *(const float4*)(g_pA + t * 8);
    float4 pa1 = *(const float4*)(g_pA + t * 8 + 4);
    float4 pb0 = *(const float4*)(g_pB + t * 8);
    float4 pb1 = *(const float4*)(g_pB + t * 8 + 4);
    float bb[8] = {b0.x, b0.y, b0.z, b0.w, b1.x, b1.y, b1.z, b1.w};
    float pa[8] = {pa0.x, pa0.y, pa0.z, pa0.w, pa1.x, pa1.y, pa1.z, pa1.w};
    float pb[8] = {pb0.x, pb0.y, pb0.z, pb0.w, pb1.x, pb1.y, pb1.z, pb1.w};

    float a = 0.f, bs = 0.f;
#pragma unroll
    for (int e = 0; e < 8; e++) {
        float v = __bfloat162float(h8[e]) + __bfloat162float(l8[e]) + bb[e];
        a  += v * pa[e];
        bs += v * pb[e];
    }
#pragma unroll
    for (int off = 4; off > 0; off >>= 1) {
        a  += __shfl_xor_sync(0xFFFFFFFF, a, off);
        bs += __shfl_xor_sync(0xFFFFFFFF, bs, off);
    }
    if ((t & 7) == 0) { sA[t >> 3] = a; sB[t >> 3] = bs; }
    __syncthreads();

    if (t < 64) {
        float rA = 0.f, rB = 0.f;
        const float4* wr = (const float4*)(Wout + t * 16);
#pragma unroll
        for (int h4 = 0; h4 < 4; h4++) {
            float4 w = wr[h4];
            float s0 = sA[h4 * 4 + 0], s1 = sA[h4 * 4 + 1], s2 = sA[h4 * 4 + 2], s3 = sA[h4 * 4 + 3];
            float u0 = sB[h4 * 4 + 0], u1 = sB[h4 * 4 + 1], u2 = sB[h4 * 4 + 2], u3 = sB[h4 * 4 + 3];
            rA += s0 * w.x + s1 * w.y + s2 * w.z + s3 * w.w;
            rB += u0 * w.x + u1 * w.y + u2 * w.z + u3 * w.w;
        }
        float yv = 0.f;
#pragma unroll
        for (int s = 0; s < 16; s++)
            yv += g_ypart[((size_t)s * 2048 + row) * 128 + z * 64 + t];
        float extra = yv + (z ? 0.f : bout[t]);
        rA = 0.5f * rA + extra;
        rB = 0.5f * rB + extra;
        if (z == 0) { g_RqA[(size_t)row * 64 + t] = rA; g_RqB[(size_t)row * 64 + t] = rB; }
        else        { g_CkA[(size_t)row * 64 + t] = rA; g_CkB[(size_t)row * 64 + t] = rB; }
    }
}

// ---------------- 6) dot GEMM per (b,h): K-chunks of 32, 2 CTA/SM ----------------
#define DTILE2 (128 * PRS)
#define DOT_SMEM (4 * DTILE2)
__global__ __launch_bounds__(256, 2) void k_dot() {
    extern __shared__ char smem[];
    int bh = blockIdx.z;
    int b = bh >> 4, h = bh & 15;
    int q0 = blockIdx.y * 128;
    int n0 = blockIdx.x * 128;
    int tid = threadIdx.x;
    int wid = tid >> 5;
    int wm = wid & 3;
    int wn = wid >> 2;

    wmma::fragment<wmma::accumulator, 16, 16, 16, float> acc[2][4];
#pragma unroll
    for (int i = 0; i < 2; i++)
#pragma unroll
        for (int j = 0; j < 4; j++) wmma::fill_fragment(acc[i][j], 0.f);

    for (int c = 0; c < 2; c++) {
        int r = tid >> 1;
        int f2 = (tid & 1) * 2;
        if (c) __syncthreads();
#pragma unroll
        for (int ff = 0; ff < 2; ff++) {
            int f = f2 + ff;
            size_t qoff = ((size_t)(b * PQ + q0 + r)) * 1024 + h * 64 + c * 32 + f * 8;
            size_t koff = ((size_t)(b * PQ + n0 + r)) * 1024 + h * 64 + c * 32 + f * 8;
            *(float4*)(smem + 0 * DTILE2 + r * PRS + f * 16) = *(const float4*)(g_qhi + qoff);
            *(float4*)(smem + 1 * DTILE2 + r * PRS + f * 16) = *(const float4*)(g_qlo + qoff);
            *(float4*)(smem + 2 * DTILE2 + r * PRS + f * 16) = *(const float4*)(g_khi + koff);
            *(float4*)(smem + 3 * DTILE2 + r * PRS + f * 16) = *(const float4*)(g_klo + koff);
        }
        __syncthreads();

        const __nv_bfloat16* pAh = (const __nv_bfloat16*)(smem + 0 * DTILE2);
        const __nv_bfloat16* pAl = (const __nv_bfloat16*)(smem + 1 * DTILE2);
        const __nv_bfloat16* pBh = (const __nv_bfloat16*)(smem + 2 * DTILE2);
        const __nv_bfloat16* pBl = (const __nv_bfloat16*)(smem + 3 * DTILE2);
#pragma unroll
        for (int ks = 0; ks < 2; ks++) {
            wmma::fragment<wmma::matrix_a, 16, 16, 16, __nv_bfloat16, wmma::row_major> ah[2], al[2];
            wmma::fragment<wmma::matrix_b, 16, 16, 16, __nv_bfloat16, wmma::col_major> bh[4], bl[4];
#pragma unroll
            for (int i = 0; i < 2; i++) {
                int mrow = wm * 32 + i * 16;
                wmma::load_matrix_sync(ah[i], pAh + mrow * PLD + ks * 16, PLD);
                wmma::load_matrix_sync(al[i], pAl + mrow * PLD + ks * 16, PLD);
            }
#pragma unroll
            for (int j = 0; j < 4; j++) {
                int nrow = wn * 64 + j * 16;
                wmma::load_matrix_sync(bh[j], pBh + nrow * PLD + ks * 16, PLD);
                wmma::load_matrix_sync(bl[j], pBl + nrow * PLD + ks * 16, PLD);
            }
#pragma unroll
            for (int i = 0; i < 2; i++)
#pragma unroll
                for (int j = 0; j < 4; j++) {
                    wmma::mma_sync(acc[i][j], ah[i], bh[j], acc[i][j]);
                    wmma::mma_sync(acc[i][j], ah[i], bl[j], acc[i][j]);
                    wmma::mma_sync(acc[i][j], al[i], bh[j], acc[i][j]);
                }
        }
    }
    float* outb = g_dot + ((size_t)(b * NH + h) * PQ) * PQ;
#pragma unroll
    for (int i = 0; i < 2; i++)
#pragma unroll
        for (int j = 0; j < 4; j++) {
            float* p = outb + (size_t)(q0 + wm * 32 + i * 16) * PQ + n0 + wn * 64 + j * 16;
            wmma::store_matrix_sync(p, acc[i][j], PQ, wmma::mem_row_major);
        }
}

// ---------------- 7) epilogue: k-packed FMA2, 2 CTAs per (b,q) ----------------
__global__ __launch_bounds__(256) void k_epilogue(const float* __restrict__ Wout,
                                                  float* __restrict__ out) {
    __shared__ float As[16][260];          // 256 k + pad
    int k0 = blockIdx.x * 256;
    int q  = blockIdx.y;
    int b  = blockIdx.z;
    int tid = threadIdx.x;

    // load dot[b,h,q,k0:k0+256] -> As[h][k]
#pragma unroll
    for (int it = 0; it < 4; it++) {
        int idx = it * 256 + tid;          // 1024 float4 = 16h x 64
        int h = idx >> 6, k4 = idx & 63;
        float4 v = *(const float4*)(g_dot + ((size_t)(b * NH + h) * PQ + q) * PQ + k0 + k4 * 4);
        *(float4*)&As[h][k4 * 4] = v;
    }
    __syncthreads();

    int dp   = (tid & 31) * 2;             // 2 consecutive d
    int kgrp = tid >> 5;                   // 0..7
    // hoisted duplicated weights: w0[h] = (W[dp][h], W[dp][h]), w1 same for dp+1
    unsigned long long w0[16], w1[16];
#pragma unroll
    for (int h = 0; h < 16; h++) {
        float wa = Wout[(dp + 0) * 16 + h];
        float wb = Wout[(dp + 1) * 16 + h];
        w0[h] = pk2(wa, wa);
        w1[h] = pk2(wb, wb);
    }

    size_t rowq = (size_t)b * PQ + q;
    float rqA0 = g_RqA[rowq * 64 + dp],     rqA1 = g_RqA[rowq * 64 + dp + 1];
    float rqB0 = g_RqB[rowq * 64 + dp],     rqB1 = g_RqB[rowq * 64 + dp + 1];
    const float* ckb = (q == PQ - 1 ? g_CkB : g_CkA) + (size_t)b * PQ * 64;
    float* obase = out + (rowq * PQ + k0) * 64;

#pragma unroll 4
    for (int i = 0; i < 16; i++) {
        int k = (kgrp + 8 * i) * 2;        // pair (k, k+1), local to this 256-chunk
        unsigned long long acc0 = 0ull, acc1 = 0ull;   // packed over (k, k+1)
#pragma unroll
        for (int h = 0; h < 16; h++) {
            unsigned long long a = *(const unsigned long long*)&As[h][k];  // broadcast LDS.64
            FMA2(acc0, a, w0[h], acc0);
            FMA2(acc1, a, w1[h], acc1);
        }
        float a0k0, a0k1, a1k0, a1k1;
        upk2(a0k0, a0k1, acc0);            // d=dp   at k, k+1
        upk2(a1k0, a1k1, acc1);            // d=dp+1 at k, k+1
        int kg0 = k0 + k, kg1 = k0 + k + 1;
        float rq00 = (kg0 == PQ - 1) ? rqB0 : rqA0;
        float rq01 = (kg0 == PQ - 1) ? rqB1 : rqA1;
        float rq10 = (kg1 == PQ - 1) ? rqB0 : rqA0;
        float rq11 = (kg1 == PQ - 1) ? rqB1 : rqA1;
        float2 ck0 = *(const float2*)(ckb + (size_t)kg0 * 64 + dp);
        float2 ck1 = *(const float2*)(ckb + (size_t)kg1 * 64 + dp);
        float2 o0, o1;
        o0.x = a0k0 + rq00 + ck0.x;
        o0.y = a1k0 + rq01 + ck0.y;
        o1.x = a0k1 + rq10 + ck1.x;
        o1.y = a1k1 + rq11 + ck1.y;
        *(float2*)(obase + (size_t)k * 64 + dp)       = o0;
        *(float2*)(obase + (size_t)(k + 1) * 64 + dp) = o1;
    }
}

extern "C" void kernel_launch(void* const* d_in, const int* in_sizes, int n_in,
                              void* d_out, int out_size) {
    const float* x    = (const float*)d_in[0];
    const float* Wq   = (const float*)d_in[1];
    const float* Wk   = (const float*)d_in[2];
    const float* Wpos = (const float*)d_in[3];
    const float* bpos = (const float*)d_in[4];
    const float* qb   = (const float*)d_in[5];
    const float* kb   = (const float*)d_in[6];
    const float* Wout = (const float*)d_in[7];
    const float* bout = (const float*)d_in[8];
    const float* Wyq  = (const float*)d_in[9];
    const float* Wyk  = (const float*)d_in[10];
    float* out = (float*)d_out;
    (void)in_sizes; (void)n_in; (void)out_size;

    cudaFuncSetAttribute(k_projmma, cudaFuncAttributeMaxDynamicSharedMemorySize, PRJ_SMEM);
    cudaFuncSetAttribute(k_dot,     cudaFuncAttributeMaxDynamicSharedMemorySize, DOT_SMEM);

    k_front   <<<4100, 256>>>(x, Wpos, bpos, Wq, Wk);
    k_projmma <<<dim3(8, 16, 2), 256, PRJ_SMEM>>>();
    k_y       <<<dim3(16, 16), 256>>>(Wyq, Wyk);
    k_dot     <<<dim3(4, 4, 64), 256, DOT_SMEM>>>();
    k_scalars <<<dim3(2048, 2), 128>>>(qb, kb, Wout, bout);
    k_epilogue<<<dim3(2, 512, 4), 256>>>(Wout, out);
}

// round 15
// speedup vs baseline: 1.0834x; 1.0834x over previous
#include <cuda_runtime.h>
#include <cuda_bf16.h>
#include <mma.h>
#include <math.h>
#include <stdint.h>

using namespace nvcuda;

#define NB   4
#define DIMD 1024
#define PQ   512
#define NH   16
#define PD   64

// ---- static device scratch ----
static __device__ float g_xds  [NB * PQ * DIMD];
static __device__ float g_pA   [DIMD];
static __device__ float g_pB   [DIMD];
static __device__ float g_ypart[16 * 2048 * 128];
static __device__ float g_RqA  [NB * PQ * PD];
static __device__ float g_RqB  [NB * PQ * PD];
static __device__ float g_CkA  [NB * PQ * PD];
static __device__ float g_CkB  [NB * PQ * PD];
static __device__ float g_dot  [(size_t)NB * NH * PQ * PQ];   // 64 MB
// bf16 hi/lo splits
static __device__ __nv_bfloat16 g_xhi [2048 * 1024];
static __device__ __nv_bfloat16 g_xlo [2048 * 1024];
static __device__ __nv_bfloat16 g_wqhi[1024 * 1024];
static __device__ __nv_bfloat16 g_wqlo[1024 * 1024];
static __device__ __nv_bfloat16 g_wkhi[1024 * 1024];
static __device__ __nv_bfloat16 g_wklo[1024 * 1024];
static __device__ __nv_bfloat16 g_qhi [2048 * 1024];
static __device__ __nv_bfloat16 g_qlo [2048 * 1024];
static __device__ __nv_bfloat16 g_khi [2048 * 1024];
static __device__ __nv_bfloat16 g_klo [2048 * 1024];

// ---- cp.async helpers ----
#define CP_ASYNC16(dst, src) \
    asm volatile("cp.async.cg.shared.global [%0], [%1], 16;" :: "r"(dst), "l"(src))
#define CP_COMMIT() asm volatile("cp.async.commit_group;")
#define CP_WAIT(n)  asm volatile("cp.async.wait_group %0;" :: "n"(n))

// ---- packed f32x2 FMA ----
#define FMA2(d, a, b, c) \
    asm("fma.rn.f32x2 %0, %1, %2, %3;" : "=l"(d) : "l"(a), "l"(b), "l"(c))
__device__ __forceinline__ unsigned long long pk2(float x, float y) {
    unsigned long long r;
    asm("mov.b64 %0, {%1, %2};" : "=l"(r) : "f"(x), "f"(y));
    return r;
}
__device__ __forceinline__ void upk2(float& x, float& y, unsigned long long r) {
    asm("mov.b64 {%0, %1}, %2;" : "=f"(x), "=f"(y) : "l"(r));
}

// ---- bf16 hi/lo split ----
__device__ __forceinline__ void split_store(const float4& v, __nv_bfloat16* hi,
                                            __nv_bfloat16* lo, size_t idx4) {
    float a[4] = {v.x, v.y, v.z, v.w};
    __nv_bfloat16 h[4], l[4];
#pragma unroll
    for (int e = 0; e < 4; e++) {
        h[e] = __float2bfloat16(a[e]);
        l[e] = __float2bfloat16(a[e] - __bfloat162float(h[e]));
    }
    *(uint2*)(hi + idx4 * 4) = *(uint2*)h;
    *(uint2*)(lo + idx4 * 4) = *(uint2*)l;
}

// ---------------- 1) front kernel: pool+split(x) | posenc | split(W) ----------------
__global__ void k_front(const float* __restrict__ x,
                        const float* __restrict__ Wpos, const float* __restrict__ bpos,
                        const float* __restrict__ Wq, const float* __restrict__ Wk) {
    int bx = blockIdx.x;
    int tid = threadIdx.x;
    if (bx < 2048) {
        int gid = bx * 256 + tid;
        int d4 = gid & 255;
        int bp = gid >> 8;
        const float4* xin = reinterpret_cast<const float4*>(x);
        size_t base = (size_t)bp * 4 * 256 + d4;
        float4 r0 = xin[base], r1 = xin[base + 256], r2 = xin[base + 512], r3 = xin[base + 768];
        float4 o;
        o.x = (r0.x + r1.x + r2.x + r3.x) * 0.25f;
        o.y = (r0.y + r1.y + r2.y + r3.y) * 0.25f;
        o.z = (r0.z + r1.z + r2.z + r3.z) * 0.25f;
        o.w = (r0.w + r1.w + r2.w + r3.w) * 0.25f;
        size_t idx4 = (size_t)bp * 256 + d4;
        reinterpret_cast<float4*>(g_xds)[idx4] = o;
        split_store(o, g_xhi, g_xlo, idx4);
    } else if (bx < 2052) {
        int hc = (bx - 2048) * 256 + tid;
        if (hc >= DIMD) return;
        float s1 = 0.f, s2 = 0.f;
#pragma unroll
        for (int j = 0; j < 32; j++) s1 += Wpos[hc * 64 + j];
#pragma unroll
        for (int j = 32; j < 64; j++) s2 += Wpos[hc * 64 + j];
        g_pA[hc] = s1 - s2 + bpos[hc];
        g_pB[hc] = s1 + bpos[hc];
    } else {
        int z = (bx - 2052) >> 10;
        int gid = ((bx - 2052) & 1023) * 256 + tid;
        const float4* src = reinterpret_cast<const float4*>(z ? Wk : Wq);
        __nv_bfloat16* hi = z ? g_wkhi : g_wqhi;
        __nv_bfloat16* lo = z ? g_wklo : g_wqlo;
        split_store(src[gid], hi, lo, gid);
    }
}

// ---------------- 3) projection GEMM ----------------
#define PRS 80
#define PLD 40
#define PTILE (128 * PRS)
#define PSTG (4 * PTILE)
#define PRJ_SMEM (2 * PSTG)

__global__ __launch_bounds__(256, 2) void k_projmma() {
    extern __shared__ char smem[];
    int tid = threadIdx.x;
    int wid = tid >> 5;
    int m0 = blockIdx.y * 128;
    int n0 = blockIdx.x * 128;
    const __nv_bfloat16* Bhi = blockIdx.z ? g_wkhi : g_wqhi;
    const __nv_bfloat16* Blo = blockIdx.z ? g_wklo : g_wqlo;
    __nv_bfloat16* Chi = blockIdx.z ? g_khi : g_qhi;
    __nv_bfloat16* Clo = blockIdx.z ? g_klo : g_qlo;

    int wm = wid & 3;
    int wn = wid >> 2;
    uint32_t sbase = (uint32_t)__cvta_generic_to_shared(smem);
    int lr = tid >> 1;
    int lh = (tid & 1) * 2;

    wmma::fragment<wmma::accumulator, 16, 16, 16, float> acc[2][4];
#pragma unroll
    for (int i = 0; i < 2; i++)
#pragma unroll
        for (int j = 0; j < 4; j++) wmma::fill_fragment(acc[i][j], 0.f);

    auto loadchunk = [&](int c, int s) {
        size_t ga = (size_t)(m0 + lr) * 1024 + c * 32;
        size_t gb = (size_t)(n0 + lr) * 1024 + c * 32;
        uint32_t rowoff = s * PSTG + lr * PRS;
#pragma unroll
        for (int f = 0; f < 2; f++) {
            int fo = lh + f;
            CP_ASYNC16(sbase + rowoff + 0 * PTILE + fo * 16, (const char*)(g_xhi + ga) + fo * 16);
            CP_ASYNC16(sbase + rowoff + 1 * PTILE + fo * 16, (const char*)(g_xlo + ga) + fo * 16);
            CP_ASYNC16(sbase + rowoff + 2 * PTILE + fo * 16, (const char*)(Bhi + gb) + fo * 16);
            CP_ASYNC16(sbase + rowoff + 3 * PTILE + fo * 16, (const char*)(Blo + gb) + fo * 16);
        }
    };

    loadchunk(0, 0);
    CP_COMMIT();

    for (int c = 0; c < 32; c++) {
        CP_WAIT(0);
        __syncthreads();
        if (c < 31) {
            loadchunk(c + 1, (c + 1) & 1);
            CP_COMMIT();
        }
        int s = c & 1;
        const __nv_bfloat16* pAh = (const __nv_bfloat16*)(smem + s * PSTG + 0 * PTILE);
        const __nv_bfloat16* pAl = (const __nv_bfloat16*)(smem + s * PSTG + 1 * PTILE);
        const __nv_bfloat16* pBh = (const __nv_bfloat16*)(smem + s * PSTG + 2 * PTILE);
        const __nv_bfloat16* pBl = (const __nv_bfloat16*)(smem + s * PSTG + 3 * PTILE);
#pragma unroll
        for (int ks = 0; ks < 2; ks++) {
            wmma::fragment<wmma::matrix_a, 16, 16, 16, __nv_bfloat16, wmma::row_major> ah[2], al[2];
            wmma::fragment<wmma::matrix_b, 16, 16, 16, __nv_bfloat16, wmma::col_major> bh[4], bl[4];
#pragma unroll
            for (int i = 0; i < 2; i++) {
                int mrow = wm * 32 + i * 16;
                wmma::load_matrix_sync(ah[i], pAh + mrow * PLD + ks * 16, PLD);
                wmma::load_matrix_sync(al[i], pAl + mrow * PLD + ks * 16, PLD);
            }
#pragma unroll
            for (int j = 0; j < 4; j++) {
                int nrow = wn * 64 + j * 16;
                wmma::load_matrix_sync(bh[j], pBh + nrow * PLD + ks * 16, PLD);
                wmma::load_matrix_sync(bl[j], pBl + nrow * PLD + ks * 16, PLD);
            }
#pragma unroll
            for (int i = 0; i < 2; i++)
#pragma unroll
                for (int j = 0; j < 4; j++) {
                    wmma::mma_sync(acc[i][j], ah[i], bh[j], acc[i][j]);
                    wmma::mma_sync(acc[i][j], ah[i], bl[j], acc[i][j]);
                    wmma::mma_sync(acc[i][j], al[i], bh[j], acc[i][j]);
                }
        }
    }
    __syncthreads();

    float* Cs = (float*)smem;
#pragma unroll
    for (int i = 0; i < 2; i++)
#pragma unroll
        for (int j = 0; j < 4; j++)
            wmma::store_matrix_sync(Cs + (wm * 32 + i * 16) * 128 + wn * 64 + j * 16,
                                    acc[i][j], 128, wmma::mem_row_major);
    __syncthreads();
#pragma unroll
    for (int it = 0; it < 16; it++) {
        int idx = it * 256 + tid;
        int r = idx >> 5, c4 = idx & 31;
        float4 v = reinterpret_cast<const float4*>(Cs)[idx];
        size_t off4 = ((size_t)(m0 + r) * 1024 + n0) / 4 + c4;
        split_store(v, Chi, Clo, off4);
    }
}

// ---------------- 4) y partials: K split 16 ways ----------------
__global__ __launch_bounds__(256) void k_y(const float* __restrict__ Wyq,
                                           const float* __restrict__ Wyk) {
    __shared__ float As[16][132];
    __shared__ float Bs[16][132];
    int ks = blockIdx.x;
    int bm = blockIdx.y * 128;
    int tid = threadIdx.x;
    int lr = tid >> 1;
    int lc = (tid & 1) * 8;
    int tx = tid & 15;
    int ty = tid >> 4;
    float acc[8][8];
#pragma unroll
    for (int i = 0; i < 8; i++)
#pragma unroll
        for (int j = 0; j < 8; j++) acc[i][j] = 0.f;

    const float* aptr = g_xds + (size_t)(bm + lr) * DIMD + ks * 64 + lc;
    const float* brow = (lr < 64) ? (Wyq + (size_t)lr * DIMD) : (Wyk + (size_t)(lr - 64) * DIMD);
    const float* bptr = brow + ks * 64 + lc;

    for (int k0 = 0; k0 < 64; k0 += 16) {
        float4 a0 = *(const float4*)(aptr + k0);
        float4 a1 = *(const float4*)(aptr + k0 + 4);
        float4 b0 = *(const float4*)(bptr + k0);
        float4 b1 = *(const float4*)(bptr + k0 + 4);
        float av8[8] = {a0.x, a0.y, a0.z, a0.w, a1.x, a1.y, a1.z, a1.w};
#pragma unroll
        for (int e = 0; e < 8; e++)
            av8[e] = 0.5f * av8[e] * (1.f + erff(av8[e] * 0.70710678118654752f));
        __syncthreads();
#pragma unroll
        for (int e = 0; e < 8; e++) As[lc + e][lr] = av8[e];
        Bs[lc + 0][lr] = b0.x; Bs[lc + 1][lr] = b0.y;
        Bs[lc + 2][lr] = b0.z; Bs[lc + 3][lr] = b0.w;
        Bs[lc + 4][lr] = b1.x; Bs[lc + 5][lr] = b1.y;
        Bs[lc + 6][lr] = b1.z; Bs[lc + 7][lr] = b1.w;
        __syncthreads();
#pragma unroll
        for (int kk = 0; kk < 16; kk++) {
            float4 af0 = *(const float4*)&As[kk][ty * 4];
            float4 af1 = *(const float4*)&As[kk][64 + ty * 4];
            float4 bf0 = *(const float4*)&Bs[kk][tx * 4];
            float4 bf1 = *(const float4*)&Bs[kk][64 + tx * 4];
            float av[8] = {af0.x, af0.y, af0.z, af0.w, af1.x, af1.y, af1.z, af1.w};
            float bv[8] = {bf0.x, bf0.y, bf0.z, bf0.w, bf1.x, bf1.y, bf1.z, bf1.w};
#pragma unroll
            for (int i = 0; i < 8; i++)
#pragma unroll
                for (int j = 0; j < 8; j++) acc[i][j] += av[i] * bv[j];
        }
    }
#pragma unroll
    for (int i = 0; i < 8; i++) {
        int r = bm + (i < 4 ? ty * 4 + i : 64 + ty * 4 + (i - 4));
        float4 v0 = make_float4(acc[i][0], acc[i][1], acc[i][2], acc[i][3]);
        float4 v1 = make_float4(acc[i][4], acc[i][5], acc[i][6], acc[i][7]);
        *(float4*)&g_ypart[((size_t)ks * 2048 + r) * 128 + tx * 4]      = v0;
        *(float4*)&g_ypart[((size_t)ks * 2048 + r) * 128 + 64 + tx * 4] = v1;
    }
}

// ---------------- 5) row/col corrections ----------------
__global__ __launch_bounds__(128) void k_scalars(const float* __restrict__ qbias,
                                                 const float* __restrict__ kbias,
                                                 const float* __restrict__ Wout,
                                                 const float* __restrict__ bout) {
    __shared__ float sA[16], sB[16];
    int row = blockIdx.x;
    int z = blockIdx.y;
    const __nv_bfloat16* shi = z ? g_khi : g_qhi;
    const __nv_bfloat16* slo = z ? g_klo : g_qlo;
    const float* bias = z ? kbias : qbias;
    int t = threadIdx.x;

    uint4 hraw = *(const uint4*)(shi + (size_t)row * DIMD + t * 8);
    uint4 lraw = *(const uint4*)(slo + (size_t)row * DIMD + t * 8);
    const __nv_bfloat16* h8 = (const __nv_bfloat16*)&hraw;
    const __nv_bfloat16* l8 = (const __nv_bfloat16*)&lraw;
    float4 b0 = *(const float4*)(bias + t * 8);
    float4 b1 = *(const float4*)(bias + t * 8 + 4);
    float4 pa0 = *(const float4*)(g_pA + t * 8);
    float4 pa1 = *(const float4*)(g_pA + t * 8 + 4);
    float4 pb0 = *(const float4*)(g_pB + t * 8);
    float4 pb1 = *(const float4*)(g_pB + t * 8 + 4);
    float bb[8] = {b0.x, b0.y, b0.z, b0.w, b1.x, b1.y, b1.z, b1.w};
    float pa[8] = {pa0.x, pa0.y, pa0.z, pa0.w, pa1.x, pa1.y, pa1.z, pa1.w};
    float pb[8] = {pb0.x, pb0.y, pb0.z, pb0.w, pb1.x, pb1.y, pb1.z, pb1.w};

    float a = 0.f, bs = 0.f;
#pragma unroll
    for (int e = 0; e < 8; e++) {
        float v = __bfloat162float(h8[e]) + __bfloat162float(l8[e]) + bb[e];
        a  += v * pa[e];
        bs += v * pb[e];
    }
#pragma unroll
    for (int off = 4; off > 0; off >>= 1) {
        a  += __shfl_xor_sync(0xFFFFFFFF, a, off);
        bs += __shfl_xor_sync(0xFFFFFFFF, bs, off);
    }
    if ((t & 7) == 0) { sA[t >> 3] = a; sB[t >> 3] = bs; }
    __syncthreads();

    if (t < 64) {
        float rA = 0.f, rB = 0.f;
        const float4* wr = (const float4*)(Wout + t * 16);
#pragma unroll
        for (int h4 = 0; h4 < 4; h4++) {
            float4 w = wr[h4];
            float s0 = sA[h4 * 4 + 0], s1 = sA[h4 * 4 + 1], s2 = sA[h4 * 4 + 2], s3 = sA[h4 * 4 + 3];
            float u0 = sB[h4 * 4 + 0], u1 = sB[h4 * 4 + 1], u2 = sB[h4 * 4 + 2], u3 = sB[h4 * 4 + 3];
            rA += s0 * w.x + s1 * w.y + s2 * w.z + s3 * w.w;
            rB += u0 * w.x + u1 * w.y + u2 * w.z + u3 * w.w;
        }
        float yv = 0.f;
#pragma unroll
        for (int s = 0; s < 16; s++)
            yv += g_ypart[((size_t)s * 2048 + row) * 128 + z * 64 + t];
        float extra = yv + (z ? 0.f : bout[t]);
        rA = 0.5f * rA + extra;
        rB = 0.5f * rB + extra;
        if (z == 0) { g_RqA[(size_t)row * 64 + t] = rA; g_RqB[(size_t)row * 64 + t] = rB; }
        else        { g_CkA[(size_t)row * 64 + t] = rA; g_CkB[(size_t)row * 64 + t] = rB; }
    }
}

// ---------------- 6) dot GEMM per (b,h) ----------------
#define DTILE2 (128 * PRS)
#define DOT_SMEM (4 * DTILE2)
__global__ __launch_bounds__(256, 2) void k_dot() {
    extern __shared__ char smem[];
    int bh = blockIdx.z;
    int b = bh >> 4, h = bh & 15;
    int q0 = blockIdx.y * 128;
    int n0 = blockIdx.x * 128;
    int tid = threadIdx.x;
    int wid = tid >> 5;
    int wm = wid & 3;
    int wn = wid >> 2;

    wmma::fragment<wmma::accumulator, 16, 16, 16, float> acc[2][4];
#pragma unroll
    for (int i = 0; i < 2; i++)
#pragma unroll
        for (int j = 0; j < 4; j++) wmma::fill_fragment(acc[i][j], 0.f);

    for (int c = 0; c < 2; c++) {
        int r = tid >> 1;
        int f2 = (tid & 1) * 2;
        if (c) __syncthreads();
#pragma unroll
        for (int ff = 0; ff < 2; ff++) {
            int f = f2 + ff;
            size_t qoff = ((size_t)(b * PQ + q0 + r)) * 1024 + h * 64 + c * 32 + f * 8;
            size_t koff = ((size_t)(b * PQ + n0 + r)) * 1024 + h * 64 + c * 32 + f * 8;
            *(float4*)(smem + 0 * DTILE2 + r * PRS + f * 16) = *(const float4*)(g_qhi + qoff);
            *(float4*)(smem + 1 * DTILE2 + r * PRS + f * 16) = *(const float4*)(g_qlo + qoff);
            *(float4*)(smem + 2 * DTILE2 + r * PRS + f * 16) = *(const float4*)(g_khi + koff);
            *(float4*)(smem + 3 * DTILE2 + r * PRS + f * 16) = *(const float4*)(g_klo + koff);
        }
        __syncthreads();

        const __nv_bfloat16* pAh = (const __nv_bfloat16*)(smem + 0 * DTILE2);
        const __nv_bfloat16* pAl = (const __nv_bfloat16*)(smem + 1 * DTILE2);
        const __nv_bfloat16* pBh = (const __nv_bfloat16*)(smem + 2 * DTILE2);
        const __nv_bfloat16* pBl = (const __nv_bfloat16*)(smem + 3 * DTILE2);
#pragma unroll
        for (int ks = 0; ks < 2; ks++) {
            wmma::fragment<wmma::matrix_a, 16, 16, 16, __nv_bfloat16, wmma::row_major> ah[2], al[2];
            wmma::fragment<wmma::matrix_b, 16, 16, 16, __nv_bfloat16, wmma::col_major> bh[4], bl[4];
#pragma unroll
            for (int i = 0; i < 2; i++) {
                int mrow = wm * 32 + i * 16;
                wmma::load_matrix_sync(ah[i], pAh + mrow * PLD + ks * 16, PLD);
                wmma::load_matrix_sync(al[i], pAl + mrow * PLD + ks * 16, PLD);
            }
#pragma unroll
            for (int j = 0; j < 4; j++) {
                int nrow = wn * 64 + j * 16;
                wmma::load_matrix_sync(bh[j], pBh + nrow * PLD + ks * 16, PLD);
                wmma::load_matrix_sync(bl[j], pBl + nrow * PLD + ks * 16, PLD);
            }
#pragma unroll
            for (int i = 0; i < 2; i++)
#pragma unroll
                for (int j = 0; j < 4; j++) {
                    wmma::mma_sync(acc[i][j], ah[i], bh[j], acc[i][j]);
                    wmma::mma_sync(acc[i][j], ah[i], bl[j], acc[i][j]);
                    wmma::mma_sync(acc[i][j], al[i], bh[j], acc[i][j]);
                }
        }
    }
    float* outb = g_dot + ((size_t)(b * NH + h) * PQ) * PQ;
#pragma unroll
    for (int i = 0; i < 2; i++)
#pragma unroll
        for (int j = 0; j < 4; j++) {
            float* p = outb + (size_t)(q0 + wm * 32 + i * 16) * PQ + n0 + wn * 64 + j * 16;
            wmma::store_matrix_sync(p, acc[i][j], PQ, wmma::mem_row_major);
        }
}

// ---------------- 7) epilogue: duplicated-smem FMA2, float4 stores (R13 structure) ----------------
#define EROW 1040                              // floats per smem row (1024 dup + pad)
#define EPI_SMEM (16 * EROW * 4)               // 66560 bytes
__global__ __launch_bounds__(256) void k_epilogue(const float* __restrict__ Wout,
                                                  float* __restrict__ out) {
    extern __shared__ float Asd[];             // [16][EROW], duplicated k values
    int q = blockIdx.x;
    int b = blockIdx.y;
    int tid = threadIdx.x;
#pragma unroll
    for (int it = 0; it < 8; it++) {
        int idx = it * 256 + tid;              // 2048 float4 = 16h x 128
        int h = idx >> 7, k4 = idx & 127;
        float4 v = *(const float4*)(g_dot + ((size_t)(b * NH + h) * PQ + q) * PQ + k4 * 4);
        float* dst = &Asd[h * EROW + k4 * 8];
        ((float4*)dst)[0] = make_float4(v.x, v.x, v.y, v.y);
        ((float4*)dst)[1] = make_float4(v.z, v.z, v.w, v.w);
    }
    __syncthreads();

    int d0   = (tid & 15) * 4;
    int kgrp = tid >> 4;
    unsigned long long w01[16], w23[16];
#pragma unroll
    for (int h = 0; h < 16; h++) {
        w01[h] = pk2(Wout[(d0 + 0) * 16 + h], Wout[(d0 + 1) * 16 + h]);
        w23[h] = pk2(Wout[(d0 + 2) * 16 + h], Wout[(d0 + 3) * 16 + h]);
    }

    size_t rowq = (size_t)b * PQ + q;
    float4 rqA = *(const float4*)(g_RqA + rowq * 64 + d0);
    float4 rqB = *(const float4*)(g_RqB + rowq * 64 + d0);
    const float* ckb = (q == PQ - 1 ? g_CkB : g_CkA) + (size_t)b * PQ * 64;
    float* obase = out + rowq * PQ * 64;

#pragma unroll 4
    for (int i = 0; i < 32; i++) {
        int k = kgrp + 16 * i;
        unsigned long long a01 = 0ull, a23 = 0ull;
#pragma unroll
        for (int h = 0; h < 16; h++) {
            unsigned long long aa = *(const unsigned long long*)&Asd[h * EROW + 2 * k];
            FMA2(a01, aa, w01[h], a01);
            FMA2(a23, aa, w23[h], a23);
        }
        float ax, ay, az, aw;
        upk2(ax, ay, a01);
        upk2(az, aw, a23);
        float4 rq = (k == PQ - 1) ? rqB : rqA;
        float4 ck = *(const float4*)(ckb + (size_t)k * 64 + d0);
        float4 o;
        o.x = ax + rq.x + ck.x;
        o.y = ay + rq.y + ck.y;
        o.z = az + rq.z + ck.z;
        o.w = aw + rq.w + ck.w;
        *(float4*)(obase + (size_t)k * 64 + d0) = o;
    }
}

extern "C" void kernel_launch(void* const* d_in, const int* in_sizes, int n_in,
                              void* d_out, int out_size) {
    const float* x    = (const float*)d_in[0];
    const float* Wq   = (const float*)d_in[1];
    const float* Wk   = (const float*)d_in[2];
    const float* Wpos = (const float*)d_in[3];
    const float* bpos = (const float*)d_in[4];
    const float* qb   = (const float*)d_in[5];
    const float* kb   = (const float*)d_in[6];
    const float* Wout = (const float*)d_in[7];
    const float* bout = (const float*)d_in[8];
    const float* Wyq  = (const float*)d_in[9];
    const float* Wyk  = (const float*)d_in[10];
    float* out = (float*)d_out;
    (void)in_sizes; (void)n_in; (void)out_size;

    cudaFuncSetAttribute(k_projmma,  cudaFuncAttributeMaxDynamicSharedMemorySize, PRJ_SMEM);
    cudaFuncSetAttribute(k_dot,      cudaFuncAttributeMaxDynamicSharedMemorySize, DOT_SMEM);
    cudaFuncSetAttribute(k_epilogue, cudaFuncAttributeMaxDynamicSharedMemorySize, EPI_SMEM);

    k_front   <<<4100, 256>>>(x, Wpos, bpos, Wq, Wk);
    k_projmma <<<dim3(8, 16, 2), 256, PRJ_SMEM>>>();
    k_y       <<<dim3(16, 16), 256>>>(Wyq, Wyk);
    k_dot     <<<dim3(4, 4, 64), 256, DOT_SMEM>>>();
    k_scalars <<<dim3(2048, 2), 128>>>(qb, kb, Wout, bout);
    k_epilogue<<<dim3(512, 4), 256, EPI_SMEM>>>(Wout, out);
}

// round 16
// speedup vs baseline: 1.1712x; 1.0810x over previous
#include <cuda_runtime.h>
#include <cuda_bf16.h>
#include <mma.h>
#include <math.h>
#include <stdint.h>

using namespace nvcuda;

#define NB   4
#define DIMD 1024
#define PQ   512
#define NH   16
#define PD   64

// ---- static device scratch ----
static __device__ float g_xds  [NB * PQ * DIMD];
static __device__ float g_pA   [DIMD];
static __device__ float g_pB   [DIMD];
static __device__ float g_ypart[16 * 2048 * 128];
static __device__ float g_RqA  [NB * PQ * PD];
static __device__ float g_RqB  [NB * PQ * PD];
static __device__ float g_CkA  [NB * PQ * PD];
static __device__ float g_CkB  [NB * PQ * PD];
static __device__ float g_dot  [(size_t)NB * NH * PQ * PQ];   // 64 MB
// bf16 hi/lo splits
static __device__ __nv_bfloat16 g_xhi [2048 * 1024];
static __device__ __nv_bfloat16 g_xlo [2048 * 1024];
static __device__ __nv_bfloat16 g_wqhi[1024 * 1024];
static __device__ __nv_bfloat16 g_wqlo[1024 * 1024];
static __device__ __nv_bfloat16 g_wkhi[1024 * 1024];
static __device__ __nv_bfloat16 g_wklo[1024 * 1024];
static __device__ __nv_bfloat16 g_qhi [2048 * 1024];
static __device__ __nv_bfloat16 g_qlo [2048 * 1024];
static __device__ __nv_bfloat16 g_khi [2048 * 1024];
static __device__ __nv_bfloat16 g_klo [2048 * 1024];

// ---- cp.async helpers ----
#define CP_ASYNC16(dst, src) \
    asm volatile("cp.async.cg.shared.global [%0], [%1], 16;" :: "r"(dst), "l"(src))
#define CP_COMMIT() asm volatile("cp.async.commit_group;")
#define CP_WAIT(n)  asm volatile("cp.async.wait_group %0;" :: "n"(n))

// ---- packed f32x2 FMA ----
#define FMA2(d, a, b, c) \
    asm("fma.rn.f32x2 %0, %1, %2, %3;" : "=l"(d) : "l"(a), "l"(b), "l"(c))
__device__ __forceinline__ unsigned long long pk2(float x, float y) {
    unsigned long long r;
    asm("mov.b64 %0, {%1, %2};" : "=l"(r) : "f"(x), "f"(y));
    return r;
}
__device__ __forceinline__ void upk2(float& x, float& y, unsigned long long r) {
    asm("mov.b64 {%0, %1}, %2;" : "=f"(x), "=f"(y) : "l"(r));
}

// ---- bf16 hi/lo split ----
__device__ __forceinline__ void split_store(const float4& v, __nv_bfloat16* hi,
                                            __nv_bfloat16* lo, size_t idx4) {
    float a[4] = {v.x, v.y, v.z, v.w};
    __nv_bfloat16 h[4], l[4];
#pragma unroll
    for (int e = 0; e < 4; e++) {
        h[e] = __float2bfloat16(a[e]);
        l[e] = __float2bfloat16(a[e] - __bfloat162float(h[e]));
    }
    *(uint2*)(hi + idx4 * 4) = *(uint2*)h;
    *(uint2*)(lo + idx4 * 4) = *(uint2*)l;
}

// ---------------- 1) front kernel: pool+split(x) | posenc | split(W) ----------------
__global__ void k_front(const float* __restrict__ x,
                        const float* __restrict__ Wpos, const float* __restrict__ bpos,
                        const float* __restrict__ Wq, const float* __restrict__ Wk) {
    int bx = blockIdx.x;
    int tid = threadIdx.x;
    if (bx < 2048) {
        int gid = bx * 256 + tid;
        int d4 = gid & 255;
        int bp = gid >> 8;
        const float4* xin = reinterpret_cast<const float4*>(x);
        size_t base = (size_t)bp * 4 * 256 + d4;
        float4 r0 = xin[base], r1 = xin[base + 256], r2 = xin[base + 512], r3 = xin[base + 768];
        float4 o;
        o.x = (r0.x + r1.x + r2.x + r3.x) * 0.25f;
        o.y = (r0.y + r1.y + r2.y + r3.y) * 0.25f;
        o.z = (r0.z + r1.z + r2.z + r3.z) * 0.25f;
        o.w = (r0.w + r1.w + r2.w + r3.w) * 0.25f;
        size_t idx4 = (size_t)bp * 256 + d4;
        reinterpret_cast<float4*>(g_xds)[idx4] = o;
        split_store(o, g_xhi, g_xlo, idx4);
    } else if (bx < 2052) {
        int hc = (bx - 2048) * 256 + tid;
        if (hc >= DIMD) return;
        float s1 = 0.f, s2 = 0.f;
#pragma unroll
        for (int j = 0; j < 32; j++) s1 += Wpos[hc * 64 + j];
#pragma unroll
        for (int j = 32; j < 64; j++) s2 += Wpos[hc * 64 + j];
        g_pA[hc] = s1 - s2 + bpos[hc];
        g_pB[hc] = s1 + bpos[hc];
    } else {
        int z = (bx - 2052) >> 10;
        int gid = ((bx - 2052) & 1023) * 256 + tid;
        const float4* src = reinterpret_cast<const float4*>(z ? Wk : Wq);
        __nv_bfloat16* hi = z ? g_wkhi : g_wqhi;
        __nv_bfloat16* lo = z ? g_wklo : g_wqlo;
        split_store(src[gid], hi, lo, gid);
    }
}

// ---------------- 3) projection GEMM ----------------
#define PRS 80
#define PLD 40
#define PTILE (128 * PRS)
#define PSTG (4 * PTILE)
#define PRJ_SMEM (2 * PSTG)

__global__ __launch_bounds__(256, 2) void k_projmma() {
    extern __shared__ char smem[];
    int tid = threadIdx.x;
    int wid = tid >> 5;
    int m0 = blockIdx.y * 128;
    int n0 = blockIdx.x * 128;
    const __nv_bfloat16* Bhi = blockIdx.z ? g_wkhi : g_wqhi;
    const __nv_bfloat16* Blo = blockIdx.z ? g_wklo : g_wqlo;
    __nv_bfloat16* Chi = blockIdx.z ? g_khi : g_qhi;
    __nv_bfloat16* Clo = blockIdx.z ? g_klo : g_qlo;

    int wm = wid & 3;
    int wn = wid >> 2;
    uint32_t sbase = (uint32_t)__cvta_generic_to_shared(smem);
    int lr = tid >> 1;
    int lh = (tid & 1) * 2;

    wmma::fragment<wmma::accumulator, 16, 16, 16, float> acc[2][4];
#pragma unroll
    for (int i = 0; i < 2; i++)
#pragma unroll
        for (int j = 0; j < 4; j++) wmma::fill_fragment(acc[i][j], 0.f);

    auto loadchunk = [&](int c, int s) {
        size_t ga = (size_t)(m0 + lr) * 1024 + c * 32;
        size_t gb = (size_t)(n0 + lr) * 1024 + c * 32;
        uint32_t rowoff = s * PSTG + lr * PRS;
#pragma unroll
        for (int f = 0; f < 2; f++) {
            int fo = lh + f;
            CP_ASYNC16(sbase + rowoff + 0 * PTILE + fo * 16, (const char*)(g_xhi + ga) + fo * 16);
            CP_ASYNC16(sbase + rowoff + 1 * PTILE + fo * 16, (const char*)(g_xlo + ga) + fo * 16);
            CP_ASYNC16(sbase + rowoff + 2 * PTILE + fo * 16, (const char*)(Bhi + gb) + fo * 16);
            CP_ASYNC16(sbase + rowoff + 3 * PTILE + fo * 16, (const char*)(Blo + gb) + fo * 16);
        }
    };

    loadchunk(0, 0);
    CP_COMMIT();

    for (int c = 0; c < 32; c++) {
        CP_WAIT(0);
        __syncthreads();
        if (c < 31) {
            loadchunk(c + 1, (c + 1) & 1);
            CP_COMMIT();
        }
        int s = c & 1;
        const __nv_bfloat16* pAh = (const __nv_bfloat16*)(smem + s * PSTG + 0 * PTILE);
        const __nv_bfloat16* pAl = (const __nv_bfloat16*)(smem + s * PSTG + 1 * PTILE);
        const __nv_bfloat16* pBh = (const __nv_bfloat16*)(smem + s * PSTG + 2 * PTILE);
        const __nv_bfloat16* pBl = (const __nv_bfloat16*)(smem + s * PSTG + 3 * PTILE);
#pragma unroll
        for (int ks = 0; ks < 2; ks++) {
            wmma::fragment<wmma::matrix_a, 16, 16, 16, __nv_bfloat16, wmma::row_major> ah[2], al[2];
            wmma::fragment<wmma::matrix_b, 16, 16, 16, __nv_bfloat16, wmma::col_major> bh[4], bl[4];
#pragma unroll
            for (int i = 0; i < 2; i++) {
                int mrow = wm * 32 + i * 16;
                wmma::load_matrix_sync(ah[i], pAh + mrow * PLD + ks * 16, PLD);
                wmma::load_matrix_sync(al[i], pAl + mrow * PLD + ks * 16, PLD);
            }
#pragma unroll
            for (int j = 0; j < 4; j++) {
                int nrow = wn * 64 + j * 16;
                wmma::load_matrix_sync(bh[j], pBh + nrow * PLD + ks * 16, PLD);
                wmma::load_matrix_sync(bl[j], pBl + nrow * PLD + ks * 16, PLD);
            }
#pragma unroll
            for (int i = 0; i < 2; i++)
#pragma unroll
                for (int j = 0; j < 4; j++) {
                    wmma::mma_sync(acc[i][j], ah[i], bh[j], acc[i][j]);
                    wmma::mma_sync(acc[i][j], ah[i], bl[j], acc[i][j]);
                    wmma::mma_sync(acc[i][j], al[i], bh[j], acc[i][j]);
                }
        }
    }
    __syncthreads();

    float* Cs = (float*)smem;
#pragma unroll
    for (int i = 0; i < 2; i++)
#pragma unroll
        for (int j = 0; j < 4; j++)
            wmma::store_matrix_sync(Cs + (wm * 32 + i * 16) * 128 + wn * 64 + j * 16,
                                    acc[i][j], 128, wmma::mem_row_major);
    __syncthreads();
#pragma unroll
    for (int it = 0; it < 16; it++) {
        int idx = it * 256 + tid;
        int r = idx >> 5, c4 = idx & 31;
        float4 v = reinterpret_cast<const float4*>(Cs)[idx];
        size_t off4 = ((size_t)(m0 + r) * 1024 + n0) / 4 + c4;
        split_store(v, Chi, Clo, off4);
    }
}

// ---------------- 4) y partials: K split 16 ways ----------------
__global__ __launch_bounds__(256) void k_y(const float* __restrict__ Wyq,
                                           const float* __restrict__ Wyk) {
    __shared__ float As[16][132];
    __shared__ float Bs[16][132];
    int ks = blockIdx.x;
    int bm = blockIdx.y * 128;
    int tid = threadIdx.x;
    int lr = tid >> 1;
    int lc = (tid & 1) * 8;
    int tx = tid & 15;
    int ty = tid >> 4;
    float acc[8][8];
#pragma unroll
    for (int i = 0; i < 8; i++)
#pragma unroll
        for (int j = 0; j < 8; j++) acc[i][j] = 0.f;

    const float* aptr = g_xds + (size_t)(bm + lr) * DIMD + ks * 64 + lc;
    const float* brow = (lr < 64) ? (Wyq + (size_t)lr * DIMD) : (Wyk + (size_t)(lr - 64) * DIMD);
    const float* bptr = brow + ks * 64 + lc;

    for (int k0 = 0; k0 < 64; k0 += 16) {
        float4 a0 = *(const float4*)(aptr + k0);
        float4 a1 = *(const float4*)(aptr + k0 + 4);
        float4 b0 = *(const float4*)(bptr + k0);
        float4 b1 = *(const float4*)(bptr + k0 + 4);
        float av8[8] = {a0.x, a0.y, a0.z, a0.w, a1.x, a1.y, a1.z, a1.w};
#pragma unroll
        for (int e = 0; e < 8; e++)
            av8[e] = 0.5f * av8[e] * (1.f + erff(av8[e] * 0.70710678118654752f));
        __syncthreads();
#pragma unroll
        for (int e = 0; e < 8; e++) As[lc + e][lr] = av8[e];
        Bs[lc + 0][lr] = b0.x; Bs[lc + 1][lr] = b0.y;
        Bs[lc + 2][lr] = b0.z; Bs[lc + 3][lr] = b0.w;
        Bs[lc + 4][lr] = b1.x; Bs[lc + 5][lr] = b1.y;
        Bs[lc + 6][lr] = b1.z; Bs[lc + 7][lr] = b1.w;
        __syncthreads();
#pragma unroll
        for (int kk = 0; kk < 16; kk++) {
            float4 af0 = *(const float4*)&As[kk][ty * 4];
            float4 af1 = *(const float4*)&As[kk][64 + ty * 4];
            float4 bf0 = *(const float4*)&Bs[kk][tx * 4];
            float4 bf1 = *(const float4*)&Bs[kk][64 + tx * 4];
            float av[8] = {af0.x, af0.y, af0.z, af0.w, af1.x, af1.y, af1.z, af1.w};
            float bv[8] = {bf0.x, bf0.y, bf0.z, bf0.w, bf1.x, bf1.y, bf1.z, bf1.w};
#pragma unroll
            for (int i = 0; i < 8; i++)
#pragma unroll
                for (int j = 0; j < 8; j++) acc[i][j] += av[i] * bv[j];
        }
    }
#pragma unroll
    for (int i = 0; i < 8; i++) {
        int r = bm + (i < 4 ? ty * 4 + i : 64 + ty * 4 + (i - 4));
        float4 v0 = make_float4(acc[i][0], acc[i][1], acc[i][2], acc[i][3]);
        float4 v1 = make_float4(acc[i][4], acc[i][5], acc[i][6], acc[i][7]);
        *(float4*)&g_ypart[((size_t)ks * 2048 + r) * 128 + tx * 4]      = v0;
        *(float4*)&g_ypart[((size_t)ks * 2048 + r) * 128 + 64 + tx * 4] = v1;
    }
}

// ---------------- 5) row/col corrections ----------------
__global__ __launch_bounds__(128) void k_scalars(const float* __restrict__ qbias,
                                                 const float* __restrict__ kbias,
                                                 const float* __restrict__ Wout,
                                                 const float* __restrict__ bout) {
    __shared__ float sA[16], sB[16];
    int row = blockIdx.x;
    int z = blockIdx.y;
    const __nv_bfloat16* shi = z ? g_khi : g_qhi;
    const __nv_bfloat16* slo = z ? g_klo : g_qlo;
    const float* bias = z ? kbias : qbias;
    int t = threadIdx.x;

    uint4 hraw = *(const uint4*)(shi + (size_t)row * DIMD + t * 8);
    uint4 lraw = *(const uint4*)(slo + (size_t)row * DIMD + t * 8);
    const __nv_bfloat16* h8 = (const __nv_bfloat16*)&hraw;
    const __nv_bfloat16* l8 = (const __nv_bfloat16*)&lraw;
    float4 b0 = *(const float4*)(bias + t * 8);
    float4 b1 = *(const float4*)(bias + t * 8 + 4);
    float4 pa0 = *(const float4*)(g_pA + t * 8);
    float4 pa1 = *(const float4*)(g_pA + t * 8 + 4);
    float4 pb0 = *(const float4*)(g_pB + t * 8);
    float4 pb1 = *(const float4*)(g_pB + t * 8 + 4);
    float bb[8] = {b0.x, b0.y, b0.z, b0.w, b1.x, b1.y, b1.z, b1.w};
    float pa[8] = {pa0.x, pa0.y, pa0.z, pa0.w, pa1.x, pa1.y, pa1.z, pa1.w};
    float pb[8] = {pb0.x, pb0.y, pb0.z, pb0.w, pb1.x, pb1.y, pb1.z, pb1.w};

    float a = 0.f, bs = 0.f;
#pragma unroll
    for (int e = 0; e < 8; e++) {
        float v = __bfloat162float(h8[e]) + __bfloat162float(l8[e]) + bb[e];
        a  += v * pa[e];
        bs += v * pb[e];
    }
#pragma unroll
    for (int off = 4; off > 0; off >>= 1) {
        a  += __shfl_xor_sync(0xFFFFFFFF, a, off);
        bs += __shfl_xor_sync(0xFFFFFFFF, bs, off);
    }
    if ((t & 7) == 0) { sA[t >> 3] = a; sB[t >> 3] = bs; }
    __syncthreads();

    if (t < 64) {
        float rA = 0.f, rB = 0.f;
        const float4* wr = (const float4*)(Wout + t * 16);
#pragma unroll
        for (int h4 = 0; h4 < 4; h4++) {
            float4 w = wr[h4];
            float s0 = sA[h4 * 4 + 0], s1 = sA[h4 * 4 + 1], s2 = sA[h4 * 4 + 2], s3 = sA[h4 * 4 + 3];
            float u0 = sB[h4 * 4 + 0], u1 = sB[h4 * 4 + 1], u2 = sB[h4 * 4 + 2], u3 = sB[h4 * 4 + 3];
            rA += s0 * w.x + s1 * w.y + s2 * w.z + s3 * w.w;
            rB += u0 * w.x + u1 * w.y + u2 * w.z + u3 * w.w;
        }
        float yv = 0.f;
#pragma unroll
        for (int s = 0; s < 16; s++)
            yv += g_ypart[((size_t)s * 2048 + row) * 128 + z * 64 + t];
        float extra = yv + (z ? 0.f : bout[t]);
        rA = 0.5f * rA + extra;
        rB = 0.5f * rB + extra;
        if (z == 0) { g_RqA[(size_t)row * 64 + t] = rA; g_RqB[(size_t)row * 64 + t] = rB; }
        else        { g_CkA[(size_t)row * 64 + t] = rA; g_CkB[(size_t)row * 64 + t] = rB; }
    }
}

// ---------------- 6) dot GEMM per (b,h) ----------------
#define DTILE2 (128 * PRS)
#define DOT_SMEM (4 * DTILE2)
__global__ __launch_bounds__(256, 2) void k_dot() {
    extern __shared__ char smem[];
    int bh = blockIdx.z;
    int b = bh >> 4, h = bh & 15;
    int q0 = blockIdx.y * 128;
    int n0 = blockIdx.x * 128;
    int tid = threadIdx.x;
    int wid = tid >> 5;
    int wm = wid & 3;
    int wn = wid >> 2;

    wmma::fragment<wmma::accumulator, 16, 16, 16, float> acc[2][4];
#pragma unroll
    for (int i = 0; i < 2; i++)
#pragma unroll
        for (int j = 0; j < 4; j++) wmma::fill_fragment(acc[i][j], 0.f);

    for (int c = 0; c < 2; c++) {
        int r = tid >> 1;
        int f2 = (tid & 1) * 2;
        if (c) __syncthreads();
#pragma unroll
        for (int ff = 0; ff < 2; ff++) {
            int f = f2 + ff;
            size_t qoff = ((size_t)(b * PQ + q0 + r)) * 1024 + h * 64 + c * 32 + f * 8;
            size_t koff = ((size_t)(b * PQ + n0 + r)) * 1024 + h * 64 + c * 32 + f * 8;
            *(float4*)(smem + 0 * DTILE2 + r * PRS + f * 16) = *(const float4*)(g_qhi + qoff);
            *(float4*)(smem + 1 * DTILE2 + r * PRS + f * 16) = *(const float4*)(g_qlo + qoff);
            *(float4*)(smem + 2 * DTILE2 + r * PRS + f * 16) = *(const float4*)(g_khi + koff);
            *(float4*)(smem + 3 * DTILE2 + r * PRS + f * 16) = *(const float4*)(g_klo + koff);
        }
        __syncthreads();

        const __nv_bfloat16* pAh = (const __nv_bfloat16*)(smem + 0 * DTILE2);
        const __nv_bfloat16* pAl = (const __nv_bfloat16*)(smem + 1 * DTILE2);
        const __nv_bfloat16* pBh = (const __nv_bfloat16*)(smem + 2 * DTILE2);
        const __nv_bfloat16* pBl = (const __nv_bfloat16*)(smem + 3 * DTILE2);
#pragma unroll
        for (int ks = 0; ks < 2; ks++) {
            wmma::fragment<wmma::matrix_a, 16, 16, 16, __nv_bfloat16, wmma::row_major> ah[2], al[2];
            wmma::fragment<wmma::matrix_b, 16, 16, 16, __nv_bfloat16, wmma::col_major> bh[4], bl[4];
#pragma unroll
            for (int i = 0; i < 2; i++) {
                int mrow = wm * 32 + i * 16;
                wmma::load_matrix_sync(ah[i], pAh + mrow * PLD + ks * 16, PLD);
                wmma::load_matrix_sync(al[i], pAl + mrow * PLD + ks * 16, PLD);
            }
#pragma unroll
            for (int j = 0; j < 4; j++) {
                int nrow = wn * 64 + j * 16;
                wmma::load_matrix_sync(bh[j], pBh + nrow * PLD + ks * 16, PLD);
                wmma::load_matrix_sync(bl[j], pBl + nrow * PLD + ks * 16, PLD);
            }
#pragma unroll
            for (int i = 0; i < 2; i++)
#pragma unroll
                for (int j = 0; j < 4; j++) {
                    wmma::mma_sync(acc[i][j], ah[i], bh[j], acc[i][j]);
                    wmma::mma_sync(acc[i][j], ah[i], bl[j], acc[i][j]);
                    wmma::mma_sync(acc[i][j], al[i], bh[j], acc[i][j]);
                }
        }
    }
    float* outb = g_dot + ((size_t)(b * NH + h) * PQ) * PQ;
#pragma unroll
    for (int i = 0; i < 2; i++)
#pragma unroll
        for (int j = 0; j < 4; j++) {
            float* p = outb + (size_t)(q0 + wm * 32 + i * 16) * PQ + n0 + wn * 64 + j * 16;
            wmma::store_matrix_sync(p, acc[i][j], PQ, wmma::mem_row_major);
        }
}

// ---------------- 7) epilogue: R13 structure + streaming cache hints ----------------
__global__ __launch_bounds__(256) void k_epilogue(const float* __restrict__ Wout,
                                                  float* __restrict__ out) {
    __shared__ float As[16][516];
    int q = blockIdx.x;
    int b = blockIdx.y;
    int tid = threadIdx.x;
#pragma unroll
    for (int it = 0; it < 8; it++) {
        int idx = it * 256 + tid;
        int h = idx >> 7, k4 = idx & 127;
        float4 v = __ldcs((const float4*)(g_dot + ((size_t)(b * NH + h) * PQ + q) * PQ + k4 * 4));
        *(float4*)&As[h][k4 * 4] = v;
    }
    __syncthreads();

    int d0   = (tid & 15) * 4;
    int kgrp = tid >> 4;
    unsigned long long w01[16], w23[16];
#pragma unroll
    for (int h = 0; h < 16; h++) {
        w01[h] = pk2(Wout[(d0 + 0) * 16 + h], Wout[(d0 + 1) * 16 + h]);
        w23[h] = pk2(Wout[(d0 + 2) * 16 + h], Wout[(d0 + 3) * 16 + h]);
    }

    size_t rowq = (size_t)b * PQ + q;
    float4 rqA = *(const float4*)(g_RqA + rowq * 64 + d0);
    float4 rqB = *(const float4*)(g_RqB + rowq * 64 + d0);
    const float* ckb = (q == PQ - 1 ? g_CkB : g_CkA) + (size_t)b * PQ * 64;
    float* obase = out + rowq * PQ * 64;

#pragma unroll 4
    for (int i = 0; i < 32; i++) {
        int k = kgrp + 16 * i;
        unsigned long long a01 = 0ull, a23 = 0ull;
#pragma unroll
        for (int h = 0; h < 16; h++) {
            float a = As[h][k];
            unsigned long long aa = pk2(a, a);
            FMA2(a01, aa, w01[h], a01);
            FMA2(a23, aa, w23[h], a23);
        }
        float ax, ay, az, aw;
        upk2(ax, ay, a01);
        upk2(az, aw, a23);
        float4 rq = (k == PQ - 1) ? rqB : rqA;
        float4 ck = *(const float4*)(ckb + (size_t)k * 64 + d0);
        float4 o;
        o.x = ax + rq.x + ck.x;
        o.y = ay + rq.y + ck.y;
        o.z = az + rq.z + ck.z;
        o.w = aw + rq.w + ck.w;
        __stcs((float4*)(obase + (size_t)k * 64 + d0), o);
    }
}

extern "C" void kernel_launch(void* const* d_in, const int* in_sizes, int n_in,
                              void* d_out, int out_size) {
    const float* x    = (const float*)d_in[0];
    const float* Wq   = (const float*)d_in[1];
    const float* Wk   = (const float*)d_in[2];
    const float* Wpos = (const float*)d_in[3];
    const float* bpos = (const float*)d_in[4];
    const float* qb   = (const float*)d_in[5];
    const float* kb   = (const float*)d_in[6];
    const float* Wout = (const float*)d_in[7];
    const float* bout = (const float*)d_in[8];
    const float* Wyq  = (const float*)d_in[9];
    const float* Wyk  = (const float*)d_in[10];
    float* out = (float*)d_out;
    (void)in_sizes; (void)n_in; (void)out_size;

    cudaFuncSetAttribute(k_projmma, cudaFuncAttributeMaxDynamicSharedMemorySize, PRJ_SMEM);
    cudaFuncSetAttribute(k_dot,     cudaFuncAttributeMaxDynamicSharedMemorySize, DOT_SMEM);

    k_front   <<<4100, 256>>>(x, Wpos, bpos, Wq, Wk);
    k_projmma <<<dim3(8, 16, 2), 256, PRJ_SMEM>>>();
    k_y       <<<dim3(16, 16), 256>>>(Wyq, Wyk);
    k_dot     <<<dim3(4, 4, 64), 256, DOT_SMEM>>>();
    k_scalars <<<dim3(2048, 2), 128>>>(qb, kb, Wout, bout);
    k_epilogue<<<dim3(512, 4), 256>>>(Wout, out);
}